// round 1
// baseline (speedup 1.0000x reference)
#include <cuda_runtime.h>

#define MAX_N 100000
#define FDIM 64

// Scratch: Q = X@W1 + (X*X)@W2, consumed by the SpMM gather.
// 100000 * 64 * 4B = 25.6 MB -> L2-resident on GB300 (126 MB L2).
__device__ float g_Q[(size_t)MAX_N * FDIM];

// ---------------------------------------------------------------------------
// Dense kernel: per 128-row tile, compute
//   acc1 = X @ W1          -> out = acc1 + (b1+b2)
//   acc2 = (X*X) @ W2      -> Q   = acc1 + acc2
// W1, W2 (16 KB each) + X tile (32 KB) in shared memory. 256 threads,
// each thread owns an 8-row x 4-col register tile (64 fp32 accumulators).
// ---------------------------------------------------------------------------
__global__ __launch_bounds__(256) void gnn_dense(
    const float* __restrict__ X,
    const float* __restrict__ W1, const float* __restrict__ b1,
    const float* __restrict__ W2, const float* __restrict__ b2,
    float* __restrict__ out, int N)
{
    extern __shared__ float smem[];
    float* W1s = smem;          // 64*64
    float* W2s = smem + 4096;   // 64*64
    float* Xs  = smem + 8192;   // 128*64

    const int tid = threadIdx.x;

    // Load W1, W2 (1024 float4 each), 256 threads -> 4 iters
    #pragma unroll
    for (int i = tid; i < 1024; i += 256) {
        reinterpret_cast<float4*>(W1s)[i] = reinterpret_cast<const float4*>(W1)[i];
        reinterpret_cast<float4*>(W2s)[i] = reinterpret_cast<const float4*>(W2)[i];
    }

    const int row0 = blockIdx.x * 128;
    // Load X tile: 128 rows * 16 float4
    #pragma unroll
    for (int i = tid; i < 128 * 16; i += 256) {
        const int r  = i >> 4;
        const int gr = row0 + r;
        float4 v = make_float4(0.f, 0.f, 0.f, 0.f);
        if (gr < N) v = reinterpret_cast<const float4*>(X)[(size_t)gr * 16 + (i & 15)];
        reinterpret_cast<float4*>(Xs)[i] = v;
    }
    __syncthreads();

    const int rg  = (tid >> 4) * 8;   // first row of this thread's tile
    const int cg4 = tid & 15;         // float4 column index (col = cg4*4)

    float acc1[8][4];
    float acc2[8][4];
    #pragma unroll
    for (int i = 0; i < 8; ++i)
        #pragma unroll
        for (int j = 0; j < 4; ++j) { acc1[i][j] = 0.f; acc2[i][j] = 0.f; }

    #pragma unroll 4
    for (int k = 0; k < 64; ++k) {
        const float4 w1 = reinterpret_cast<const float4*>(W1s + k * 64)[cg4];
        const float4 w2 = reinterpret_cast<const float4*>(W2s + k * 64)[cg4];
        #pragma unroll
        for (int i = 0; i < 8; ++i) {
            const float x  = Xs[(rg + i) * 64 + k];
            const float x2 = x * x;
            acc1[i][0] = fmaf(x,  w1.x, acc1[i][0]);
            acc1[i][1] = fmaf(x,  w1.y, acc1[i][1]);
            acc1[i][2] = fmaf(x,  w1.z, acc1[i][2]);
            acc1[i][3] = fmaf(x,  w1.w, acc1[i][3]);
            acc2[i][0] = fmaf(x2, w2.x, acc2[i][0]);
            acc2[i][1] = fmaf(x2, w2.y, acc2[i][1]);
            acc2[i][2] = fmaf(x2, w2.z, acc2[i][2]);
            acc2[i][3] = fmaf(x2, w2.w, acc2[i][3]);
        }
    }

    // bias = b1 + b2
    const int c = cg4 * 4;
    float4 bb;
    bb.x = __ldg(b1 + c + 0) + __ldg(b2 + c + 0);
    bb.y = __ldg(b1 + c + 1) + __ldg(b2 + c + 1);
    bb.z = __ldg(b1 + c + 2) + __ldg(b2 + c + 2);
    bb.w = __ldg(b1 + c + 3) + __ldg(b2 + c + 3);

    #pragma unroll
    for (int i = 0; i < 8; ++i) {
        const int gr = row0 + rg + i;
        if (gr < N) {
            float4 o, q;
            o.x = acc1[i][0] + bb.x;  q.x = acc1[i][0] + acc2[i][0];
            o.y = acc1[i][1] + bb.y;  q.y = acc1[i][1] + acc2[i][1];
            o.z = acc1[i][2] + bb.z;  q.z = acc1[i][2] + acc2[i][2];
            o.w = acc1[i][3] + bb.w;  q.w = acc1[i][3] + acc2[i][3];
            reinterpret_cast<float4*>(out)[(size_t)gr * 16 + cg4] = o;
            reinterpret_cast<float4*>(g_Q)[(size_t)gr * 16 + cg4] = q;
        }
    }
}

// ---------------------------------------------------------------------------
// SpMM scatter: out[rows[e]] += vals[e] * Q[cols[e]]
// 16 threads per edge; each thread handles one float4 chunk of the 64-wide
// feature row (coalesced 256B gather per edge) and 4 scalar atomicAdds
// (return value unused -> ptxas emits RED.ADD.F32).
// ---------------------------------------------------------------------------
__global__ __launch_bounds__(256) void gnn_spmm(
    const int* __restrict__ rows,
    const int* __restrict__ cols,
    const float* __restrict__ vals,
    float* out, int E)
{
    const int idx  = blockIdx.x * blockDim.x + threadIdx.x;
    const int e    = idx >> 4;
    if (e >= E) return;
    const int part = idx & 15;

    const int   r = __ldg(rows + e);
    const int   c = __ldg(cols + e);
    const float v = __ldg(vals + e);

    const float4 q = __ldg(reinterpret_cast<const float4*>(g_Q) + (size_t)c * 16 + part);

    float* p = out + (size_t)r * 64 + part * 4;
    atomicAdd(p + 0, v * q.x);
    atomicAdd(p + 1, v * q.y);
    atomicAdd(p + 2, v * q.z);
    atomicAdd(p + 3, v * q.w);
}

extern "C" void kernel_launch(void* const* d_in, const int* in_sizes, int n_in,
                              void* d_out, int out_size)
{
    const int*   rows = (const int*)  d_in[0];
    const int*   cols = (const int*)  d_in[1];
    const float* vals = (const float*)d_in[2];
    const float* X    = (const float*)d_in[3];
    const float* W1   = (const float*)d_in[4];
    const float* b1   = (const float*)d_in[5];
    const float* W2   = (const float*)d_in[6];
    const float* b2   = (const float*)d_in[7];
    float* out = (float*)d_out;

    const int E = in_sizes[0];
    const int N = in_sizes[3] / FDIM;

    // 64 KB dynamic smem for the dense kernel (idempotent, capture-safe).
    cudaFuncSetAttribute(gnn_dense, cudaFuncAttributeMaxDynamicSharedMemorySize, 65536);

    const int blocksD = (N + 127) / 128;
    gnn_dense<<<blocksD, 256, 65536>>>(X, W1, b1, W2, b2, out, N);

    const long long work = (long long)E * 16;
    const int blocksS = (int)((work + 255) / 256);
    gnn_spmm<<<blocksS, 256>>>(rows, cols, vals, out, E);
}

// round 2
// speedup vs baseline: 1.5704x; 1.5704x over previous
#include <cuda_runtime.h>

#define MAX_N 100000
#define FDIM 64

// Scratch: Q = X@W1 + (X*X)@W2, consumed by the SpMM gather.
// 100000 * 64 * 4B = 25.6 MB -> L2-resident on GB300 (126 MB L2).
__device__ float g_Q[(size_t)MAX_N * FDIM];

// ---------------------------------------------------------------------------
// Dense kernel: per 128-row tile, compute
//   acc1 = X @ W1          -> out = acc1 + (b1+b2)
//   acc2 = (X*X) @ W2      -> Q   = acc1 + acc2
// ---------------------------------------------------------------------------
__global__ __launch_bounds__(256) void gnn_dense(
    const float* __restrict__ X,
    const float* __restrict__ W1, const float* __restrict__ b1,
    const float* __restrict__ W2, const float* __restrict__ b2,
    float* __restrict__ out, int N)
{
    extern __shared__ float smem[];
    float* W1s = smem;          // 64*64
    float* W2s = smem + 4096;   // 64*64
    float* Xs  = smem + 8192;   // 128*64

    const int tid = threadIdx.x;

    #pragma unroll
    for (int i = tid; i < 1024; i += 256) {
        reinterpret_cast<float4*>(W1s)[i] = reinterpret_cast<const float4*>(W1)[i];
        reinterpret_cast<float4*>(W2s)[i] = reinterpret_cast<const float4*>(W2)[i];
    }

    const int row0 = blockIdx.x * 128;
    #pragma unroll
    for (int i = tid; i < 128 * 16; i += 256) {
        const int r  = i >> 4;
        const int gr = row0 + r;
        float4 v = make_float4(0.f, 0.f, 0.f, 0.f);
        if (gr < N) v = reinterpret_cast<const float4*>(X)[(size_t)gr * 16 + (i & 15)];
        reinterpret_cast<float4*>(Xs)[i] = v;
    }
    __syncthreads();

    const int rg  = (tid >> 4) * 8;
    const int cg4 = tid & 15;

    float acc1[8][4];
    float acc2[8][4];
    #pragma unroll
    for (int i = 0; i < 8; ++i)
        #pragma unroll
        for (int j = 0; j < 4; ++j) { acc1[i][j] = 0.f; acc2[i][j] = 0.f; }

    #pragma unroll 4
    for (int k = 0; k < 64; ++k) {
        const float4 w1 = reinterpret_cast<const float4*>(W1s + k * 64)[cg4];
        const float4 w2 = reinterpret_cast<const float4*>(W2s + k * 64)[cg4];
        #pragma unroll
        for (int i = 0; i < 8; ++i) {
            const float x  = Xs[(rg + i) * 64 + k];
            const float x2 = x * x;
            acc1[i][0] = fmaf(x,  w1.x, acc1[i][0]);
            acc1[i][1] = fmaf(x,  w1.y, acc1[i][1]);
            acc1[i][2] = fmaf(x,  w1.z, acc1[i][2]);
            acc1[i][3] = fmaf(x,  w1.w, acc1[i][3]);
            acc2[i][0] = fmaf(x2, w2.x, acc2[i][0]);
            acc2[i][1] = fmaf(x2, w2.y, acc2[i][1]);
            acc2[i][2] = fmaf(x2, w2.z, acc2[i][2]);
            acc2[i][3] = fmaf(x2, w2.w, acc2[i][3]);
        }
    }

    const int c = cg4 * 4;
    float4 bb;
    bb.x = __ldg(b1 + c + 0) + __ldg(b2 + c + 0);
    bb.y = __ldg(b1 + c + 1) + __ldg(b2 + c + 1);
    bb.z = __ldg(b1 + c + 2) + __ldg(b2 + c + 2);
    bb.w = __ldg(b1 + c + 3) + __ldg(b2 + c + 3);

    #pragma unroll
    for (int i = 0; i < 8; ++i) {
        const int gr = row0 + rg + i;
        if (gr < N) {
            float4 o, q;
            o.x = acc1[i][0] + bb.x;  q.x = acc1[i][0] + acc2[i][0];
            o.y = acc1[i][1] + bb.y;  q.y = acc1[i][1] + acc2[i][1];
            o.z = acc1[i][2] + bb.z;  q.z = acc1[i][2] + acc2[i][2];
            o.w = acc1[i][3] + bb.w;  q.w = acc1[i][3] + acc2[i][3];
            reinterpret_cast<float4*>(out)[(size_t)gr * 16 + cg4] = o;
            reinterpret_cast<float4*>(g_Q)[(size_t)gr * 16 + cg4] = q;
        }
    }
}

// Vectorized 16B float atomic-add (sm_90+): one L1 wavefront per 4 floats.
__device__ __forceinline__ void red_add_v4(float* p, float4 v) {
    asm volatile("red.global.add.v4.f32 [%0], {%1, %2, %3, %4};"
                 :: "l"(p), "f"(v.x), "f"(v.y), "f"(v.z), "f"(v.w)
                 : "memory");
}

// ---------------------------------------------------------------------------
// SpMM scatter: out[rows[e]] += vals[e] * Q[cols[e]]
// 8 threads per edge; each thread handles two float4 chunks of the 64-wide
// feature row (2x 16B gather + 2x red.v4.f32).
// ---------------------------------------------------------------------------
__global__ __launch_bounds__(256) void gnn_spmm(
    const int* __restrict__ rows,
    const int* __restrict__ cols,
    const float* __restrict__ vals,
    float* out, int E)
{
    const int idx  = blockIdx.x * blockDim.x + threadIdx.x;
    const int e    = idx >> 3;
    if (e >= E) return;
    const int part = (idx & 7) * 2;   // first float4 index of this thread's pair

    const int   r = __ldg(rows + e);
    const int   c = __ldg(cols + e);
    const float v = __ldg(vals + e);

    const float4* qrow = reinterpret_cast<const float4*>(g_Q) + (size_t)c * 16 + part;
    const float4 q0 = __ldg(qrow + 0);
    const float4 q1 = __ldg(qrow + 1);

    float* p = out + (size_t)r * 64 + part * 4;
    red_add_v4(p + 0, make_float4(v * q0.x, v * q0.y, v * q0.z, v * q0.w));
    red_add_v4(p + 4, make_float4(v * q1.x, v * q1.y, v * q1.z, v * q1.w));
}

extern "C" void kernel_launch(void* const* d_in, const int* in_sizes, int n_in,
                              void* d_out, int out_size)
{
    const int*   rows = (const int*)  d_in[0];
    const int*   cols = (const int*)  d_in[1];
    const float* vals = (const float*)d_in[2];
    const float* X    = (const float*)d_in[3];
    const float* W1   = (const float*)d_in[4];
    const float* b1   = (const float*)d_in[5];
    const float* W2   = (const float*)d_in[6];
    const float* b2   = (const float*)d_in[7];
    float* out = (float*)d_out;

    const int E = in_sizes[0];
    const int N = in_sizes[3] / FDIM;

    cudaFuncSetAttribute(gnn_dense, cudaFuncAttributeMaxDynamicSharedMemorySize, 65536);

    const int blocksD = (N + 127) / 128;
    gnn_dense<<<blocksD, 256, 65536>>>(X, W1, b1, W2, b2, out, N);

    const long long work = (long long)E * 8;
    const int blocksS = (int)((work + 255) / 256);
    gnn_spmm<<<blocksS, 256>>>(rows, cols, vals, out, E);
}

// round 3
// speedup vs baseline: 1.6605x; 1.0574x over previous
#include <cuda_runtime.h>

#define MAX_N 100000
#define MAX_E 1200000
#define FDIM 64

// Scratch (device globals; no allocation allowed in kernel_launch).
__device__ float g_Q[(size_t)MAX_N * FDIM];      // Q = X@W1 + (X*X)@W2
__device__ int   g_cnt[MAX_N];                   // per-row edge count (histogram)
__device__ int   g_rowstart[MAX_N];              // exclusive scan of g_cnt
__device__ int   g_cursor[MAX_N];                // scatter cursor; == row end after scatter
__device__ int2  g_edges[MAX_E];                 // binned (col, val-as-int) per row
__device__ int   g_bsum[128];                    // block sums for the scan

// ---------------------------------------------------------------------------
// Dense kernel + fused edge histogram.
//   acc1 = X @ W1          -> out = acc1 + (b1+b2)
//   acc2 = (X*X) @ W2      -> Q   = acc1 + acc2
// The histogram (grid-stride REDG over rows[]) is memory-pipe work hidden
// under the FFMA-bound GEMM loop.
// ---------------------------------------------------------------------------
__global__ __launch_bounds__(256) void gnn_dense_hist(
    const float* __restrict__ X,
    const float* __restrict__ W1, const float* __restrict__ b1,
    const float* __restrict__ W2, const float* __restrict__ b2,
    const int* __restrict__ rows,
    float* __restrict__ out, int N, int E)
{
    extern __shared__ float smem[];
    float* W1s = smem;          // 64*64
    float* W2s = smem + 4096;   // 64*64
    float* Xs  = smem + 8192;   // 128*64

    const int tid = threadIdx.x;

    #pragma unroll
    for (int i = tid; i < 1024; i += 256) {
        reinterpret_cast<float4*>(W1s)[i] = reinterpret_cast<const float4*>(W1)[i];
        reinterpret_cast<float4*>(W2s)[i] = reinterpret_cast<const float4*>(W2)[i];
    }

    const int row0 = blockIdx.x * 128;
    #pragma unroll
    for (int i = tid; i < 128 * 16; i += 256) {
        const int r  = i >> 4;
        const int gr = row0 + r;
        float4 v = make_float4(0.f, 0.f, 0.f, 0.f);
        if (gr < N) v = reinterpret_cast<const float4*>(X)[(size_t)gr * 16 + (i & 15)];
        reinterpret_cast<float4*>(Xs)[i] = v;
    }

    // Fused histogram: int REDG, spread addresses, hidden under FFMAs below.
    const int stride = gridDim.x * 256;
    for (int e = blockIdx.x * 256 + tid; e < E; e += stride)
        atomicAdd(&g_cnt[__ldg(rows + e)], 1);

    __syncthreads();

    const int rg  = (tid >> 4) * 8;
    const int cg4 = tid & 15;

    float acc1[8][4];
    float acc2[8][4];
    #pragma unroll
    for (int i = 0; i < 8; ++i)
        #pragma unroll
        for (int j = 0; j < 4; ++j) { acc1[i][j] = 0.f; acc2[i][j] = 0.f; }

    #pragma unroll 4
    for (int k = 0; k < 64; ++k) {
        const float4 w1 = reinterpret_cast<const float4*>(W1s + k * 64)[cg4];
        const float4 w2 = reinterpret_cast<const float4*>(W2s + k * 64)[cg4];
        #pragma unroll
        for (int i = 0; i < 8; ++i) {
            const float x  = Xs[(rg + i) * 64 + k];
            const float x2 = x * x;
            acc1[i][0] = fmaf(x,  w1.x, acc1[i][0]);
            acc1[i][1] = fmaf(x,  w1.y, acc1[i][1]);
            acc1[i][2] = fmaf(x,  w1.z, acc1[i][2]);
            acc1[i][3] = fmaf(x,  w1.w, acc1[i][3]);
            acc2[i][0] = fmaf(x2, w2.x, acc2[i][0]);
            acc2[i][1] = fmaf(x2, w2.y, acc2[i][1]);
            acc2[i][2] = fmaf(x2, w2.z, acc2[i][2]);
            acc2[i][3] = fmaf(x2, w2.w, acc2[i][3]);
        }
    }

    const int c = cg4 * 4;
    float4 bb;
    bb.x = __ldg(b1 + c + 0) + __ldg(b2 + c + 0);
    bb.y = __ldg(b1 + c + 1) + __ldg(b2 + c + 1);
    bb.z = __ldg(b1 + c + 2) + __ldg(b2 + c + 2);
    bb.w = __ldg(b1 + c + 3) + __ldg(b2 + c + 3);

    #pragma unroll
    for (int i = 0; i < 8; ++i) {
        const int gr = row0 + rg + i;
        if (gr < N) {
            float4 o, q;
            o.x = acc1[i][0] + bb.x;  q.x = acc1[i][0] + acc2[i][0];
            o.y = acc1[i][1] + bb.y;  q.y = acc1[i][1] + acc2[i][1];
            o.z = acc1[i][2] + bb.z;  q.z = acc1[i][2] + acc2[i][2];
            o.w = acc1[i][3] + bb.w;  q.w = acc1[i][3] + acc2[i][3];
            reinterpret_cast<float4*>(out)[(size_t)gr * 16 + cg4] = o;
            reinterpret_cast<float4*>(g_Q)[(size_t)gr * 16 + cg4] = q;
        }
    }
}

// ---------------------------------------------------------------------------
// Scan stage (3 small kernels): exclusive scan of g_cnt -> g_rowstart/g_cursor
// ---------------------------------------------------------------------------
__device__ __forceinline__ int warp_incl_scan(int v) {
    #pragma unroll
    for (int off = 1; off < 32; off <<= 1) {
        int u = __shfl_up_sync(0xffffffffu, v, off);
        if ((threadIdx.x & 31) >= off) v += u;
    }
    return v;
}

__global__ __launch_bounds__(1024) void scan_blocksums(int N) {
    const int i = blockIdx.x * 1024 + threadIdx.x;
    int v = (i < N) ? g_cnt[i] : 0;
    #pragma unroll
    for (int off = 16; off > 0; off >>= 1)
        v += __shfl_down_sync(0xffffffffu, v, off);
    __shared__ int ws[32];
    const int lane = threadIdx.x & 31, wid = threadIdx.x >> 5;
    if (lane == 0) ws[wid] = v;
    __syncthreads();
    if (wid == 0) {
        int x = ws[lane];
        #pragma unroll
        for (int off = 16; off > 0; off >>= 1)
            x += __shfl_down_sync(0xffffffffu, x, off);
        if (lane == 0) g_bsum[blockIdx.x] = x;
    }
}

__global__ __launch_bounds__(128) void scan_bsums(int nb) {
    __shared__ int s[128];
    const int t = threadIdx.x;
    s[t] = (t < nb) ? g_bsum[t] : 0;
    __syncthreads();
    #pragma unroll
    for (int off = 1; off < 128; off <<= 1) {
        int v = (t >= off) ? s[t - off] : 0;
        __syncthreads();
        s[t] += v;
        __syncthreads();
    }
    if (t < nb) g_bsum[t] = s[t];   // inclusive scan of block sums
}

__global__ __launch_bounds__(1024) void scan_write(int N) {
    const int t = threadIdx.x, b = blockIdx.x;
    const int i = b * 1024 + t;
    const int v = (i < N) ? g_cnt[i] : 0;
    const int lane = t & 31, wid = t >> 5;
    int inc = warp_incl_scan(v);
    __shared__ int ws[32];
    if (lane == 31) ws[wid] = inc;
    __syncthreads();
    if (wid == 0) {
        int x = ws[lane];
        x = warp_incl_scan(x);
        ws[lane] = x;
    }
    __syncthreads();
    int excl = inc - v + (wid ? ws[wid - 1] : 0) + (b ? g_bsum[b - 1] : 0);
    if (i < N) { g_rowstart[i] = excl; g_cursor[i] = excl; }
}

// ---------------------------------------------------------------------------
// Scatter edges into row bins: g_edges[slot] = (col, val)
// ---------------------------------------------------------------------------
__global__ __launch_bounds__(256) void gnn_scatter(
    const int* __restrict__ rows,
    const int* __restrict__ cols,
    const float* __restrict__ vals, int E)
{
    const int e = blockIdx.x * blockDim.x + threadIdx.x;
    if (e >= E) return;
    const int r   = __ldg(rows + e);
    const int pos = atomicAdd(&g_cursor[r], 1);
    g_edges[pos] = make_int2(__ldg(cols + e), __float_as_int(__ldg(vals + e)));
}

// ---------------------------------------------------------------------------
// CSR SpMM: one warp per row, register accumulation, no float atomics.
// out[r] += sum_j val_j * Q[col_j]   (out already holds the dense part)
// ---------------------------------------------------------------------------
__global__ __launch_bounds__(256) void gnn_spmm_csr(float* __restrict__ out, int N)
{
    const int warp = (blockIdx.x * blockDim.x + threadIdx.x) >> 5;
    if (warp >= N) return;
    const int lane = threadIdx.x & 31;

    const int start = __ldg(g_rowstart + warp);
    const int end   = __ldg(g_cursor + warp);   // == rowstart + degree after scatter
    if (end <= start) return;

    const float2* __restrict__ Q2 = reinterpret_cast<const float2*>(g_Q);
    float2 acc = make_float2(0.f, 0.f);

    int j = start;
    // 2-way unrolled: two independent gather chains in flight.
    for (; j + 1 < end; j += 2) {
        const int2 cv0 = __ldg(g_edges + j);
        const int2 cv1 = __ldg(g_edges + j + 1);
        const float2 q0 = __ldg(Q2 + (size_t)cv0.x * 32 + lane);
        const float2 q1 = __ldg(Q2 + (size_t)cv1.x * 32 + lane);
        const float v0 = __int_as_float(cv0.y);
        const float v1 = __int_as_float(cv1.y);
        acc.x = fmaf(v0, q0.x, acc.x);
        acc.y = fmaf(v0, q0.y, acc.y);
        acc.x = fmaf(v1, q1.x, acc.x);
        acc.y = fmaf(v1, q1.y, acc.y);
    }
    if (j < end) {
        const int2 cv = __ldg(g_edges + j);
        const float2 q = __ldg(Q2 + (size_t)cv.x * 32 + lane);
        const float v = __int_as_float(cv.y);
        acc.x = fmaf(v, q.x, acc.x);
        acc.y = fmaf(v, q.y, acc.y);
    }

    float2* orow = reinterpret_cast<float2*>(out) + (size_t)warp * 32 + lane;
    float2 o = *orow;
    o.x += acc.x;
    o.y += acc.y;
    *orow = o;
}

extern "C" void kernel_launch(void* const* d_in, const int* in_sizes, int n_in,
                              void* d_out, int out_size)
{
    const int*   rows = (const int*)  d_in[0];
    const int*   cols = (const int*)  d_in[1];
    const float* vals = (const float*)d_in[2];
    const float* X    = (const float*)d_in[3];
    const float* W1   = (const float*)d_in[4];
    const float* b1   = (const float*)d_in[5];
    const float* W2   = (const float*)d_in[6];
    const float* b2   = (const float*)d_in[7];
    float* out = (float*)d_out;

    const int E = in_sizes[0];
    const int N = in_sizes[3] / FDIM;

    cudaFuncSetAttribute(gnn_dense_hist, cudaFuncAttributeMaxDynamicSharedMemorySize, 65536);

    // Zero the histogram (capture-safe memset node).
    void* cnt_ptr = nullptr;
    cudaGetSymbolAddress(&cnt_ptr, g_cnt);
    cudaMemsetAsync(cnt_ptr, 0, (size_t)N * sizeof(int));

    const int blocksD = (N + 127) / 128;
    gnn_dense_hist<<<blocksD, 256, 65536>>>(X, W1, b1, W2, b2, rows, out, N, E);

    const int nb = (N + 1023) / 1024;          // 98 for N=100000
    scan_blocksums<<<nb, 1024>>>(N);
    scan_bsums<<<1, 128>>>(nb);
    scan_write<<<nb, 1024>>>(N);

    gnn_scatter<<<(E + 255) / 256, 256>>>(rows, cols, vals, E);

    const long long work = (long long)N * 32;
    gnn_spmm_csr<<<(int)((work + 255) / 256), 256>>>(out, N);
}